// round 11
// baseline (speedup 1.0000x reference)
#include <cuda_runtime.h>
#include <cuda_bf16.h>
#include <cstdint>
#include <cstddef>

// Problem constants (fixed by the reference setup)
#define BGR   256      // graphs
#define NATOM 512      // atoms per graph
#define NLIG  128      // ligand atoms per graph
#define NPROT 384      // protein atoms per graph
#define DDIM  1024     // feature dim
#define TOPK  64
#define KSEL  128      // 2*TOPK selected atoms per graph
#define NT    8        // n-tiles of 128 outputs
#define NTILE 128
#define NCHUNK 32      // K chunks of 32 bf16 cols

// ---------------------------------------------------------------------------
// Device scratch (no cudaMalloc allowed)
// ---------------------------------------------------------------------------
__device__ int   g_sel[BGR * KSEL];
__device__ float g_partial[BGR * NT * KSEL];
__device__ int   g_cnt[BGR];   // per-graph completion counters (self-resetting)
// hi/lo bf16 planes per row: [hi x1024 | lo x1024]
__device__ __nv_bfloat16 g_Ahl[(size_t)BGR * KSEL * 2 * DDIM];   // 128 MB
__device__ __nv_bfloat16 g_Whl[(size_t)DDIM * 2 * DDIM];         // 4 MB

// ---------------------------------------------------------------------------
// Helpers
// ---------------------------------------------------------------------------
__device__ __forceinline__ uint32_t smem_u32(const void* p) {
    uint32_t a;
    asm("{ .reg .u64 t; cvta.to.shared.u64 t, %1; cvt.u32.u64 %0, t; }" : "=r"(a) : "l"(p));
    return a;
}
__device__ __forceinline__ void cp_async16(uint32_t dst, const void* src) {
    asm volatile("cp.async.cg.shared.global [%0], [%1], 16;\n" :: "r"(dst), "l"(src) : "memory");
}
__device__ __forceinline__ void cp_commit() { asm volatile("cp.async.commit_group;\n" ::: "memory"); }
template <int N>
__device__ __forceinline__ void cp_wait() { asm volatile("cp.async.wait_group %0;\n" :: "n"(N) : "memory"); }

__device__ __forceinline__ void ldm4(uint32_t* r, uint32_t addr) {
    asm volatile("ldmatrix.sync.aligned.m8n8.x4.shared.b16 {%0,%1,%2,%3}, [%4];"
                 : "=r"(r[0]), "=r"(r[1]), "=r"(r[2]), "=r"(r[3]) : "r"(addr));
}
__device__ __forceinline__ void mma_bf16(float* d, const uint32_t* a, uint32_t b0, uint32_t b1) {
    asm volatile(
        "mma.sync.aligned.m16n8k16.row.col.f32.bf16.bf16.f32 "
        "{%0,%1,%2,%3}, {%4,%5,%6,%7}, {%8,%9}, {%0,%1,%2,%3};\n"
        : "+f"(d[0]), "+f"(d[1]), "+f"(d[2]), "+f"(d[3])
        : "r"(a[0]), "r"(a[1]), "r"(a[2]), "r"(a[3]), "r"(b0), "r"(b1));
}

// Accurate tanh that survives --use_fast_math.
__device__ __forceinline__ float tanh_acc(float x) {
    float e = exp2f(x * 2.8853900817779268f);
    return 1.0f - 2.0f / (e + 1.0f);
}

// hi/lo split store of 4 consecutive fp32 cols into [hi|lo] plane layout.
__device__ __forceinline__ void cvt_store4(__nv_bfloat16* dstrow, int t, float4 x) {
    const int col = t * 4;
    float xs[4] = {x.x, x.y, x.z, x.w};
    __nv_bfloat16 hi[4], lo[4];
#pragma unroll
    for (int j = 0; j < 4; j++) {
        hi[j] = __float2bfloat16(xs[j]);
        lo[j] = __float2bfloat16(xs[j] - __bfloat162float(hi[j]));
    }
    __nv_bfloat162 h01, h23, l01, l23;
    h01.x = hi[0]; h01.y = hi[1]; h23.x = hi[2]; h23.y = hi[3];
    l01.x = lo[0]; l01.y = lo[1]; l23.x = lo[2]; l23.y = lo[3];
    *(__nv_bfloat162*)(dstrow + col)            = h01;
    *(__nv_bfloat162*)(dstrow + col + 2)        = h23;
    *(__nv_bfloat162*)(dstrow + DDIM + col)     = l01;
    *(__nv_bfloat162*)(dstrow + DDIM + col + 2) = l23;
}

// ---------------------------------------------------------------------------
// Kernel 1: centroids + top-64 selection per graph. 512 threads/block:
// rank-count critical path is one key (384 compares) per thread.
// ---------------------------------------------------------------------------
__global__ void select_kernel(const float* __restrict__ coords) {
    const int b = blockIdx.x;
    const int t = threadIdx.x;

    __shared__ float cx[NATOM], cy[NATOM], cz[NATOM];
    __shared__ unsigned long long pkeys[NPROT];
    __shared__ unsigned long long lkeys[NLIG];
    __shared__ float r6[6][512];
    __shared__ float cent[6];

    const float* cg = coords + (size_t)b * NATOM * 3;
    for (int a = t; a < NATOM; a += 512) {
        cx[a] = cg[a * 3 + 0];
        cy[a] = cg[a * 3 + 1];
        cz[a] = cg[a * 3 + 2];
    }
    __syncthreads();

    float lsx = 0.f, lsy = 0.f, lsz = 0.f, psx = 0.f, psy = 0.f, psz = 0.f;
    for (int a = t; a < NATOM; a += 512) {
        if (a < NLIG) { lsx += cx[a]; lsy += cy[a]; lsz += cz[a]; }
        else          { psx += cx[a]; psy += cy[a]; psz += cz[a]; }
    }
    r6[0][t] = lsx; r6[1][t] = lsy; r6[2][t] = lsz;
    r6[3][t] = psx; r6[4][t] = psy; r6[5][t] = psz;
    __syncthreads();
    for (int s = 256; s > 0; s >>= 1) {
        if (t < s) {
#pragma unroll
            for (int c = 0; c < 6; c++) r6[c][t] += r6[c][t + s];
        }
        __syncthreads();
    }
    if (t == 0) {
        cent[0] = r6[0][0] / (float)NLIG;
        cent[1] = r6[1][0] / (float)NLIG;
        cent[2] = r6[2][0] / (float)NLIG;
        cent[3] = r6[3][0] / (float)NPROT;
        cent[4] = r6[4][0] / (float)NPROT;
        cent[5] = r6[5][0] / (float)NPROT;
    }
    __syncthreads();

    const float lcx = cent[0], lcy = cent[1], lcz = cent[2];
    const float pcx = cent[3], pcy = cent[4], pcz = cent[5];

    for (int i = t; i < NPROT; i += 512) {
        const int a = NLIG + i;
        float dx = cx[a] - lcx, dy = cy[a] - lcy, dz = cz[a] - lcz;
        float d2 = dx * dx + dy * dy + dz * dz;
        pkeys[i] = ((unsigned long long)__float_as_uint(d2) << 32) | (unsigned)a;
    }
    for (int i = t; i < NLIG; i += 512) {
        float dx = cx[i] - pcx, dy = cy[i] - pcy, dz = cz[i] - pcz;
        float d2 = dx * dx + dy * dy + dz * dz;
        lkeys[i] = ((unsigned long long)__float_as_uint(d2) << 32) | (unsigned)i;
    }
    __syncthreads();

    // rank-by-count; keys strictly distinct -> rank bijection, atomic-free
    if (t < NPROT) {
        const unsigned long long k = pkeys[t];
        int c = 0;
        for (int j = 0; j < NPROT; j++) c += (pkeys[j] < k);
        if (c < TOPK) g_sel[b * KSEL + c] = (int)(k & 0xffffffffull);
    }
    if (t < NLIG) {
        const unsigned long long k = lkeys[t];
        int c = 0;
        for (int j = 0; j < NLIG; j++) c += (lkeys[j] < k);
        if (c < TOPK) g_sel[b * KSEL + TOPK + c] = t;
    }
}

// ---------------------------------------------------------------------------
// Kernel 2: fused prep — W rows then gathered/selected h rows -> bf16 hi/lo.
// grid = DDIM + BGR*KSEL blocks, 256 threads.
// ---------------------------------------------------------------------------
__global__ void prep_kernel(const float* __restrict__ h, const float* __restrict__ W) {
    const int blk = blockIdx.x;
    const int t = threadIdx.x;
    if (blk < DDIM) {
        float4 x = *(const float4*)(W + (size_t)blk * DDIM + t * 4);
        cvt_store4(g_Whl + (size_t)blk * 2 * DDIM, t, x);
    } else {
        const int a = blk - DDIM;                 // 0..32767
        const int b = a >> 7, i = a & 127;
        const int src = b * NATOM + g_sel[b * KSEL + i];
        float4 x = *(const float4*)(h + (size_t)src * DDIM + t * 4);
        cvt_store4(g_Ahl + (size_t)a * 2 * DDIM, t, x);
    }
}

// ---------------------------------------------------------------------------
// Kernel 3: mma.sync bf16 hi/lo-split GEMM + fused bias/tanh/v-dot
// + fused per-graph softmax/Z epilogue ("last CTA of graph" pattern).
// Grid (8 n-tiles, 256 graphs), 256 threads (8 warps, 2m x 4n of 64x32).
// CTA tile: M=128 x N=128 x K=1024 (x3 split products). 2 CTAs/SM.
// SMEM: 3-stage pipelined K-chunks; XOR-swizzled 16B segments, no padding.
// One __syncthreads per chunk; warp-staggered k16 order; cp.async for c+2
// issued between the two k16 computes; precomputed ldmatrix addresses.
// ---------------------------------------------------------------------------
#define PLANE_B  (128 * 64)             // 8192 bytes per plane (128 rows x 64B)
#define ABYTES   (2 * PLANE_B)          // 16384 (A hi + A lo)
#define BUFB     (4 * PLANE_B)          // 32768 (A hi/lo + B hi/lo)
#define NSTAGE   3
#define SM_BIAS  (NSTAGE * BUFB)        // 98304 : float[128]
#define SM_V     (SM_BIAS + 512)
#define SM_SC    (SM_V + 512)           // float[128*4] (reused by fused tail)
#define SMEM_TOTAL (SM_SC + 2048)       // 101376  (x2 CTAs = 202752 <= 228K)

// swizzled in-plane byte offset for (row, seg16)
#define SWZ_OFF(row, seg) ((row) * 64 + ((((seg) ^ (((row) >> 1) & 3))) << 4))

__global__ void __launch_bounds__(256, 2)
gemm_mma_kernel(const float* __restrict__ bias, const float* __restrict__ v,
                const float* __restrict__ h, float* __restrict__ out) {
    extern __shared__ char smem[];
    const int ct = blockIdx.x;       // n-tile 0..7
    const int b  = blockIdx.y;       // graph
    const int t  = threadIdx.x;
    const int lane = t & 31, wid = t >> 5;
    const int wm = wid >> 2, wn = wid & 3;   // warp 64x32 tile coords
    const uint32_t sbase = smem_u32(smem);

    float* sbias = (float*)(smem + SM_BIAS);
    float* sv    = (float*)(smem + SM_V);
    float* ssc   = (float*)(smem + SM_SC);
    if (t < NTILE) {
        sbias[t] = bias[ct * NTILE + t];
        sv[t]    = v[ct * NTILE + t];
    }

    const char* asrc = (const char*)(g_Ahl) + (size_t)b * KSEL * 4096;    // 2048 bf16/row
    const char* bsrc = (const char*)(g_Whl) + (size_t)ct * NTILE * 4096;

    // chunk loader: 2048 x 16B segments (A: 1024, B: 1024), 8 per thread
    auto load_chunk = [&](int c, int buf) {
        const uint32_t dstbase = sbase + buf * BUFB;
        const int coff = c * 64;   // 32 bf16 = 64 B within a plane
#pragma unroll
        for (int it = 0; it < 8; it++) {
            const int s = t + it * 256;
            const bool isA = s < 1024;
            const int s2 = isA ? s : s - 1024;
            const int plane = s2 >> 9, row = (s2 >> 2) & 127, seg = s2 & 3;
            const char* src = (isA ? asrc : bsrc) + (size_t)row * 4096 + plane * 2048 + coff + seg * 16;
            const uint32_t dst = dstbase + (isA ? 0 : ABYTES) + plane * PLANE_B + SWZ_OFF(row, seg);
            cp_async16(dst, src);
        }
        cp_commit();
    };

    // per-thread ldmatrix swizzled byte offsets, precomputed for both k16 halves
    uint32_t a_off[4][2], b_off[2][2];
#pragma unroll
    for (int mt = 0; mt < 4; mt++) {
        const int row = wm * 64 + mt * 16 + (lane & 15);
        const int s0 = lane >> 4;
#pragma unroll
        for (int k16 = 0; k16 < 2; k16++)
            a_off[mt][k16] = (uint32_t)SWZ_OFF(row, s0 + 2 * k16);
    }
#pragma unroll
    for (int np = 0; np < 2; np++) {
        const int row = wn * 32 + np * 16 + (lane & 7) + ((lane >> 4) << 3);
        const int s0 = (lane >> 3) & 1;
#pragma unroll
        for (int k16 = 0; k16 < 2; k16++)
            b_off[np][k16] = (uint32_t)SWZ_OFF(row, s0 + 2 * k16);
    }

    float acc[4][4][4];
#pragma unroll
    for (int mt = 0; mt < 4; mt++)
#pragma unroll
        for (int nt = 0; nt < 4; nt++)
#pragma unroll
            for (int q = 0; q < 4; q++) acc[mt][nt][q] = 0.f;

    // compute one k16 half of the current chunk
    auto compute_k16 = [&](uint32_t abase, uint32_t bbase, int k16) {
        uint32_t Af[4][4], Bh[2][4], Bl[2][4];
#pragma unroll
        for (int mt = 0; mt < 4; mt++) ldm4(Af[mt], abase + a_off[mt][k16]);
#pragma unroll
        for (int np = 0; np < 2; np++) ldm4(Bh[np], bbase + b_off[np][k16]);
#pragma unroll
        for (int np = 0; np < 2; np++) ldm4(Bl[np], bbase + PLANE_B + b_off[np][k16]);
        // Ahi * Bhi
#pragma unroll
        for (int mt = 0; mt < 4; mt++)
#pragma unroll
            for (int np = 0; np < 2; np++) {
                mma_bf16(acc[mt][2 * np],     Af[mt], Bh[np][0], Bh[np][1]);
                mma_bf16(acc[mt][2 * np + 1], Af[mt], Bh[np][2], Bh[np][3]);
            }
        // Ahi * Blo
#pragma unroll
        for (int mt = 0; mt < 4; mt++)
#pragma unroll
            for (int np = 0; np < 2; np++) {
                mma_bf16(acc[mt][2 * np],     Af[mt], Bl[np][0], Bl[np][1]);
                mma_bf16(acc[mt][2 * np + 1], Af[mt], Bl[np][2], Bl[np][3]);
            }
        // Alo * Bhi (Af reused destructively: peak frag regs stay at 32)
#pragma unroll
        for (int mt = 0; mt < 4; mt++) ldm4(Af[mt], abase + PLANE_B + a_off[mt][k16]);
#pragma unroll
        for (int mt = 0; mt < 4; mt++)
#pragma unroll
            for (int np = 0; np < 2; np++) {
                mma_bf16(acc[mt][2 * np],     Af[mt], Bh[np][0], Bh[np][1]);
                mma_bf16(acc[mt][2 * np + 1], Af[mt], Bh[np][2], Bh[np][3]);
            }
    };

    load_chunk(0, 0);
    load_chunk(1, 1);

    const int kfirst = (wid >> 2) & 1;   // SMSP siblings (wid, wid+4) opposite
    int buf_c = 0, buf_n2 = 2;           // buffer of chunk c, buffer for chunk c+2
    for (int c = 0; c < NCHUNK; c++) {
        if (c + 1 < NCHUNK) cp_wait<1>(); else cp_wait<0>();
        __syncthreads();

        const uint32_t abase = sbase + buf_c * BUFB;
        const uint32_t bbase = abase + ABYTES;

        compute_k16(abase, bbase, kfirst);
        if (c + 2 < NCHUNK) load_chunk(c + 2, buf_n2);
        compute_k16(abase, bbase, kfirst ^ 1);

        const int nb = buf_c + 1;
        buf_c  = (nb == NSTAGE) ? 0 : nb;
        const int nn = buf_n2 + 1;
        buf_n2 = (nn == NSTAGE) ? 0 : nn;
    }

    // Epilogue: bias + tanh + v-dot, reduce over this CTA's 128 cols
#pragma unroll
    for (int mt = 0; mt < 4; mt++) {
#pragma unroll
        for (int half = 0; half < 2; half++) {
            float s = 0.f;
#pragma unroll
            for (int nt = 0; nt < 4; nt++) {
                const int n = wn * 32 + nt * 8 + 2 * (lane & 3);
                const float* a2 = &acc[mt][nt][half * 2];
                s = fmaf(sv[n],     tanh_acc(a2[0] + sbias[n]),     s);
                s = fmaf(sv[n + 1], tanh_acc(a2[1] + sbias[n + 1]), s);
            }
            s += __shfl_xor_sync(0xffffffffu, s, 1);
            s += __shfl_xor_sync(0xffffffffu, s, 2);
            if ((lane & 3) == 0) {
                const int row = wm * 64 + mt * 16 + (lane >> 2) + half * 8;
                ssc[row * 4 + wn] = s;
            }
        }
    }
    __syncthreads();
    if (t < KSEL)
        g_partial[(b * NT + ct) * KSEL + t] =
            (ssc[t * 4] + ssc[t * 4 + 1]) + (ssc[t * 4 + 2] + ssc[t * 4 + 3]);

    // ---- fused finalize: last CTA of this graph does softmax + Z ----
    __threadfence();
    __shared__ int slast;
    if (t == 0) slast = (atomicAdd(&g_cnt[b], 1) == NT - 1);
    __syncthreads();
    if (!slast) return;
    if (t == 0) g_cnt[b] = 0;   // self-reset for next graph replay

    // smem overlay on SM_SC region (2048 B): scores|alpha|red|ridx
    float* scores = ssc;              // [128]
    float* alpha  = ssc + 128;        // [128]
    float* red    = ssc + 256;        // [128]
    int*   ridx   = (int*)(ssc + 384);

    if (t < KSEL) {
        float s = 0.f;
#pragma unroll
        for (int q = 0; q < NT; q++)
            s += __ldcg(&g_partial[(b * NT + q) * KSEL + t]);
        scores[t] = s;
        red[t] = s;
        ridx[t] = b * NATOM + g_sel[b * KSEL + t];
    }
    __syncthreads();
    for (int s = 64; s > 0; s >>= 1) {
        if (t < s) red[t] = fmaxf(red[t], red[t + s]);
        __syncthreads();
    }
    const float mx = red[0];
    __syncthreads();
    if (t < KSEL) {
        float e = expf(scores[t] - mx);
        alpha[t] = e;
        red[t] = e;
    }
    __syncthreads();
    for (int s = 64; s > 0; s >>= 1) {
        if (t < s) red[t] += red[t + s];
        __syncthreads();
    }
    const float inv = 1.0f / red[0];
    __syncthreads();
    if (t < KSEL) alpha[t] *= inv;
    __syncthreads();

    const int d0 = t * 4;
    float4 zacc = make_float4(0.f, 0.f, 0.f, 0.f);
#pragma unroll 4
    for (int k = 0; k < KSEL; k++) {
        const float al = alpha[k];
        const float4 hv = *(const float4*)(h + (size_t)ridx[k] * DDIM + d0);
        zacc.x = fmaf(al, hv.x, zacc.x);
        zacc.y = fmaf(al, hv.y, zacc.y);
        zacc.z = fmaf(al, hv.z, zacc.z);
        zacc.w = fmaf(al, hv.w, zacc.w);
    }
    *(float4*)(out + (size_t)b * DDIM + d0) = zacc;
}

// ---------------------------------------------------------------------------
// Entry point
// ---------------------------------------------------------------------------
extern "C" void kernel_launch(void* const* d_in, const int* in_sizes, int n_in,
                              void* d_out, int out_size) {
    const float* h      = (const float*)d_in[0];
    const float* coords = (const float*)d_in[1];
    const float* W      = (const float*)d_in[4];
    const float* bias   = (const float*)d_in[5];
    const float* v      = (const float*)d_in[6];
    float* out = (float*)d_out;

    cudaFuncSetAttribute(gemm_mma_kernel, cudaFuncAttributeMaxDynamicSharedMemorySize, SMEM_TOTAL);

    select_kernel<<<BGR, 512>>>(coords);
    prep_kernel<<<DDIM + BGR * KSEL, 256>>>(h, W);
    gemm_mma_kernel<<<dim3(NT, BGR), 256, SMEM_TOTAL>>>(bias, v, h, out);
}

// round 14
// speedup vs baseline: 1.2051x; 1.2051x over previous
#include <cuda_runtime.h>
#include <cuda_bf16.h>
#include <cstdint>
#include <cstddef>

// Problem constants (fixed by the reference setup)
#define BGR   256      // graphs
#define NATOM 512      // atoms per graph
#define NLIG  128      // ligand atoms per graph
#define NPROT 384      // protein atoms per graph
#define DDIM  1024     // feature dim
#define TOPK  64
#define KSEL  128      // 2*TOPK selected atoms per graph
#define NT    8        // n-tiles of 128 outputs
#define NTILE 128
#define NCHUNK 32      // K chunks of 32 bf16 cols

// ---------------------------------------------------------------------------
// Device scratch (no cudaMalloc allowed)
// ---------------------------------------------------------------------------
__device__ int   g_sel[BGR * KSEL];
__device__ float g_partial[BGR * NT * KSEL];
// hi/lo bf16 planes per row: [hi x1024 | lo x1024]
__device__ __nv_bfloat16 g_Ahl[(size_t)BGR * KSEL * 2 * DDIM];   // 128 MB
__device__ __nv_bfloat16 g_Whl[(size_t)DDIM * 2 * DDIM];         // 4 MB

// ---------------------------------------------------------------------------
// Helpers
// ---------------------------------------------------------------------------
__device__ __forceinline__ uint32_t smem_u32(const void* p) {
    uint32_t a;
    asm("{ .reg .u64 t; cvta.to.shared.u64 t, %1; cvt.u32.u64 %0, t; }" : "=r"(a) : "l"(p));
    return a;
}
__device__ __forceinline__ void cp_async16(uint32_t dst, const void* src) {
    asm volatile("cp.async.cg.shared.global [%0], [%1], 16;\n" :: "r"(dst), "l"(src) : "memory");
}
__device__ __forceinline__ void cp_commit() { asm volatile("cp.async.commit_group;\n" ::: "memory"); }
template <int N>
__device__ __forceinline__ void cp_wait() { asm volatile("cp.async.wait_group %0;\n" :: "n"(N) : "memory"); }

__device__ __forceinline__ void ldm4(uint32_t* r, uint32_t addr) {
    asm volatile("ldmatrix.sync.aligned.m8n8.x4.shared.b16 {%0,%1,%2,%3}, [%4];"
                 : "=r"(r[0]), "=r"(r[1]), "=r"(r[2]), "=r"(r[3]) : "r"(addr));
}
__device__ __forceinline__ void mma_bf16(float* d, const uint32_t* a, uint32_t b0, uint32_t b1) {
    asm volatile(
        "mma.sync.aligned.m16n8k16.row.col.f32.bf16.bf16.f32 "
        "{%0,%1,%2,%3}, {%4,%5,%6,%7}, {%8,%9}, {%0,%1,%2,%3};\n"
        : "+f"(d[0]), "+f"(d[1]), "+f"(d[2]), "+f"(d[3])
        : "r"(a[0]), "r"(a[1]), "r"(a[2]), "r"(a[3]), "r"(b0), "r"(b1));
}

// Accurate tanh that survives --use_fast_math.
__device__ __forceinline__ float tanh_acc(float x) {
    float e = exp2f(x * 2.8853900817779268f);
    return 1.0f - 2.0f / (e + 1.0f);
}

// hi/lo split store of 4 consecutive fp32 cols into [hi|lo] plane layout.
__device__ __forceinline__ void cvt_store4(__nv_bfloat16* dstrow, int t, float4 x) {
    const int col = t * 4;
    float xs[4] = {x.x, x.y, x.z, x.w};
    __nv_bfloat16 hi[4], lo[4];
#pragma unroll
    for (int j = 0; j < 4; j++) {
        hi[j] = __float2bfloat16(xs[j]);
        lo[j] = __float2bfloat16(xs[j] - __bfloat162float(hi[j]));
    }
    __nv_bfloat162 h01, h23, l01, l23;
    h01.x = hi[0]; h01.y = hi[1]; h23.x = hi[2]; h23.y = hi[3];
    l01.x = lo[0]; l01.y = lo[1]; l23.x = lo[2]; l23.y = lo[3];
    *(__nv_bfloat162*)(dstrow + col)            = h01;
    *(__nv_bfloat162*)(dstrow + col + 2)        = h23;
    *(__nv_bfloat162*)(dstrow + DDIM + col)     = l01;
    *(__nv_bfloat162*)(dstrow + DDIM + col + 2) = l23;
}

// ---------------------------------------------------------------------------
// Kernel 1: centroids + top-64 selection per graph. 512 threads/block:
// rank-count critical path is one key (384 compares) per thread.
// ---------------------------------------------------------------------------
__global__ void select_kernel(const float* __restrict__ coords) {
    const int b = blockIdx.x;
    const int t = threadIdx.x;

    __shared__ float cx[NATOM], cy[NATOM], cz[NATOM];
    __shared__ unsigned long long pkeys[NPROT];
    __shared__ unsigned long long lkeys[NLIG];
    __shared__ float r6[6][512];
    __shared__ float cent[6];

    const float* cg = coords + (size_t)b * NATOM * 3;
    for (int a = t; a < NATOM; a += 512) {
        cx[a] = cg[a * 3 + 0];
        cy[a] = cg[a * 3 + 1];
        cz[a] = cg[a * 3 + 2];
    }
    __syncthreads();

    float lsx = 0.f, lsy = 0.f, lsz = 0.f, psx = 0.f, psy = 0.f, psz = 0.f;
    for (int a = t; a < NATOM; a += 512) {
        if (a < NLIG) { lsx += cx[a]; lsy += cy[a]; lsz += cz[a]; }
        else          { psx += cx[a]; psy += cy[a]; psz += cz[a]; }
    }
    r6[0][t] = lsx; r6[1][t] = lsy; r6[2][t] = lsz;
    r6[3][t] = psx; r6[4][t] = psy; r6[5][t] = psz;
    __syncthreads();
    for (int s = 256; s > 0; s >>= 1) {
        if (t < s) {
#pragma unroll
            for (int c = 0; c < 6; c++) r6[c][t] += r6[c][t + s];
        }
        __syncthreads();
    }
    if (t == 0) {
        cent[0] = r6[0][0] / (float)NLIG;
        cent[1] = r6[1][0] / (float)NLIG;
        cent[2] = r6[2][0] / (float)NLIG;
        cent[3] = r6[3][0] / (float)NPROT;
        cent[4] = r6[4][0] / (float)NPROT;
        cent[5] = r6[5][0] / (float)NPROT;
    }
    __syncthreads();

    const float lcx = cent[0], lcy = cent[1], lcz = cent[2];
    const float pcx = cent[3], pcy = cent[4], pcz = cent[5];

    for (int i = t; i < NPROT; i += 512) {
        const int a = NLIG + i;
        float dx = cx[a] - lcx, dy = cy[a] - lcy, dz = cz[a] - lcz;
        float d2 = dx * dx + dy * dy + dz * dz;
        pkeys[i] = ((unsigned long long)__float_as_uint(d2) << 32) | (unsigned)a;
    }
    for (int i = t; i < NLIG; i += 512) {
        float dx = cx[i] - pcx, dy = cy[i] - pcy, dz = cz[i] - pcz;
        float d2 = dx * dx + dy * dy + dz * dz;
        lkeys[i] = ((unsigned long long)__float_as_uint(d2) << 32) | (unsigned)i;
    }
    __syncthreads();

    // rank-by-count; keys strictly distinct -> rank bijection, atomic-free
    if (t < NPROT) {
        const unsigned long long k = pkeys[t];
        int c = 0;
        for (int j = 0; j < NPROT; j++) c += (pkeys[j] < k);
        if (c < TOPK) g_sel[b * KSEL + c] = (int)(k & 0xffffffffull);
    }
    if (t < NLIG) {
        const unsigned long long k = lkeys[t];
        int c = 0;
        for (int j = 0; j < NLIG; j++) c += (lkeys[j] < k);
        if (c < TOPK) g_sel[b * KSEL + TOPK + c] = t;
    }
}

// ---------------------------------------------------------------------------
// Kernel 2: fused prep — W rows then gathered/selected h rows -> bf16 hi/lo.
// grid = DDIM + BGR*KSEL blocks, 256 threads.
// ---------------------------------------------------------------------------
__global__ void prep_kernel(const float* __restrict__ h, const float* __restrict__ W) {
    const int blk = blockIdx.x;
    const int t = threadIdx.x;
    if (blk < DDIM) {
        float4 x = *(const float4*)(W + (size_t)blk * DDIM + t * 4);
        cvt_store4(g_Whl + (size_t)blk * 2 * DDIM, t, x);
    } else {
        const int a = blk - DDIM;                 // 0..32767
        const int b = a >> 7, i = a & 127;
        const int src = b * NATOM + g_sel[b * KSEL + i];
        float4 x = *(const float4*)(h + (size_t)src * DDIM + t * 4);
        cvt_store4(g_Ahl + (size_t)a * 2 * DDIM, t, x);
    }
}

// ---------------------------------------------------------------------------
// Kernel 3: mma.sync bf16 hi/lo-split GEMM + fused bias/tanh/v-dot.
// (R9 version, bit-for-bit: no fence/atomic tail, no extra params.)
// Grid (8 n-tiles, 256 graphs), 256 threads (8 warps, 2m x 4n of 64x32).
// CTA tile: M=128 x N=128 x K=1024 (x3 split products). 2 CTAs/SM.
// SMEM: 3-stage pipelined K-chunks; XOR-swizzled 16B segments, no padding.
// One __syncthreads per chunk; warp-staggered k16 order; cp.async for c+2
// issued between the two k16 computes; precomputed ldmatrix addresses.
// ---------------------------------------------------------------------------
#define PLANE_B  (128 * 64)             // 8192 bytes per plane (128 rows x 64B)
#define ABYTES   (2 * PLANE_B)          // 16384 (A hi + A lo)
#define BUFB     (4 * PLANE_B)          // 32768 (A hi/lo + B hi/lo)
#define NSTAGE   3
#define SM_BIAS  (NSTAGE * BUFB)        // 98304 : float[128]
#define SM_V     (SM_BIAS + 512)
#define SM_SC    (SM_V + 512)           // float[128*4]
#define SMEM_TOTAL (SM_SC + 2048)       // 101376  (x2 CTAs = 202752 <= 228K)

// swizzled in-plane byte offset for (row, seg16)
#define SWZ_OFF(row, seg) ((row) * 64 + ((((seg) ^ (((row) >> 1) & 3))) << 4))

__global__ void __launch_bounds__(256, 2)
gemm_mma_kernel(const float* __restrict__ bias, const float* __restrict__ v) {
    extern __shared__ char smem[];
    const int ct = blockIdx.x;       // n-tile 0..7
    const int b  = blockIdx.y;       // graph
    const int t  = threadIdx.x;
    const int lane = t & 31, wid = t >> 5;
    const int wm = wid >> 2, wn = wid & 3;   // warp 64x32 tile coords
    const uint32_t sbase = smem_u32(smem);

    float* sbias = (float*)(smem + SM_BIAS);
    float* sv    = (float*)(smem + SM_V);
    float* ssc   = (float*)(smem + SM_SC);
    if (t < NTILE) {
        sbias[t] = bias[ct * NTILE + t];
        sv[t]    = v[ct * NTILE + t];
    }

    const char* asrc = (const char*)(g_Ahl) + (size_t)b * KSEL * 4096;    // 2048 bf16/row
    const char* bsrc = (const char*)(g_Whl) + (size_t)ct * NTILE * 4096;

    // chunk loader: 2048 x 16B segments (A: 1024, B: 1024), 8 per thread
    auto load_chunk = [&](int c, int buf) {
        const uint32_t dstbase = sbase + buf * BUFB;
        const int coff = c * 64;   // 32 bf16 = 64 B within a plane
#pragma unroll
        for (int it = 0; it < 8; it++) {
            const int s = t + it * 256;
            const bool isA = s < 1024;
            const int s2 = isA ? s : s - 1024;
            const int plane = s2 >> 9, row = (s2 >> 2) & 127, seg = s2 & 3;
            const char* src = (isA ? asrc : bsrc) + (size_t)row * 4096 + plane * 2048 + coff + seg * 16;
            const uint32_t dst = dstbase + (isA ? 0 : ABYTES) + plane * PLANE_B + SWZ_OFF(row, seg);
            cp_async16(dst, src);
        }
        cp_commit();
    };

    // per-thread ldmatrix swizzled byte offsets, precomputed for both k16 halves
    uint32_t a_off[4][2], b_off[2][2];
#pragma unroll
    for (int mt = 0; mt < 4; mt++) {
        const int row = wm * 64 + mt * 16 + (lane & 15);
        const int s0 = lane >> 4;
#pragma unroll
        for (int k16 = 0; k16 < 2; k16++)
            a_off[mt][k16] = (uint32_t)SWZ_OFF(row, s0 + 2 * k16);
    }
#pragma unroll
    for (int np = 0; np < 2; np++) {
        const int row = wn * 32 + np * 16 + (lane & 7) + ((lane >> 4) << 3);
        const int s0 = (lane >> 3) & 1;
#pragma unroll
        for (int k16 = 0; k16 < 2; k16++)
            b_off[np][k16] = (uint32_t)SWZ_OFF(row, s0 + 2 * k16);
    }

    float acc[4][4][4];
#pragma unroll
    for (int mt = 0; mt < 4; mt++)
#pragma unroll
        for (int nt = 0; nt < 4; nt++)
#pragma unroll
            for (int q = 0; q < 4; q++) acc[mt][nt][q] = 0.f;

    // compute one k16 half of the current chunk
    auto compute_k16 = [&](uint32_t abase, uint32_t bbase, int k16) {
        uint32_t Af[4][4], Bh[2][4], Bl[2][4];
#pragma unroll
        for (int mt = 0; mt < 4; mt++) ldm4(Af[mt], abase + a_off[mt][k16]);
#pragma unroll
        for (int np = 0; np < 2; np++) ldm4(Bh[np], bbase + b_off[np][k16]);
#pragma unroll
        for (int np = 0; np < 2; np++) ldm4(Bl[np], bbase + PLANE_B + b_off[np][k16]);
        // Ahi * Bhi
#pragma unroll
        for (int mt = 0; mt < 4; mt++)
#pragma unroll
            for (int np = 0; np < 2; np++) {
                mma_bf16(acc[mt][2 * np],     Af[mt], Bh[np][0], Bh[np][1]);
                mma_bf16(acc[mt][2 * np + 1], Af[mt], Bh[np][2], Bh[np][3]);
            }
        // Ahi * Blo
#pragma unroll
        for (int mt = 0; mt < 4; mt++)
#pragma unroll
            for (int np = 0; np < 2; np++) {
                mma_bf16(acc[mt][2 * np],     Af[mt], Bl[np][0], Bl[np][1]);
                mma_bf16(acc[mt][2 * np + 1], Af[mt], Bl[np][2], Bl[np][3]);
            }
        // Alo * Bhi (Af reused destructively: peak frag regs stay at 32)
#pragma unroll
        for (int mt = 0; mt < 4; mt++) ldm4(Af[mt], abase + PLANE_B + a_off[mt][k16]);
#pragma unroll
        for (int mt = 0; mt < 4; mt++)
#pragma unroll
            for (int np = 0; np < 2; np++) {
                mma_bf16(acc[mt][2 * np],     Af[mt], Bh[np][0], Bh[np][1]);
                mma_bf16(acc[mt][2 * np + 1], Af[mt], Bh[np][2], Bh[np][3]);
            }
    };

    load_chunk(0, 0);
    load_chunk(1, 1);

    const int kfirst = (wid >> 2) & 1;   // SMSP siblings (wid, wid+4) opposite
    int buf_c = 0, buf_n2 = 2;           // buffer of chunk c, buffer for chunk c+2
    for (int c = 0; c < NCHUNK; c++) {
        if (c + 1 < NCHUNK) cp_wait<1>(); else cp_wait<0>();
        __syncthreads();

        const uint32_t abase = sbase + buf_c * BUFB;
        const uint32_t bbase = abase + ABYTES;

        compute_k16(abase, bbase, kfirst);
        if (c + 2 < NCHUNK) load_chunk(c + 2, buf_n2);
        compute_k16(abase, bbase, kfirst ^ 1);

        const int nb = buf_c + 1;
        buf_c  = (nb == NSTAGE) ? 0 : nb;
        const int nn = buf_n2 + 1;
        buf_n2 = (nn == NSTAGE) ? 0 : nn;
    }

    // Epilogue: bias + tanh + v-dot, reduce over this CTA's 128 cols
#pragma unroll
    for (int mt = 0; mt < 4; mt++) {
#pragma unroll
        for (int half = 0; half < 2; half++) {
            float s = 0.f;
#pragma unroll
            for (int nt = 0; nt < 4; nt++) {
                const int n = wn * 32 + nt * 8 + 2 * (lane & 3);
                const float* a2 = &acc[mt][nt][half * 2];
                s = fmaf(sv[n],     tanh_acc(a2[0] + sbias[n]),     s);
                s = fmaf(sv[n + 1], tanh_acc(a2[1] + sbias[n + 1]), s);
            }
            s += __shfl_xor_sync(0xffffffffu, s, 1);
            s += __shfl_xor_sync(0xffffffffu, s, 2);
            if ((lane & 3) == 0) {
                const int row = wm * 64 + mt * 16 + (lane >> 2) + half * 8;
                ssc[row * 4 + wn] = s;
            }
        }
    }
    __syncthreads();
    if (t < KSEL)
        g_partial[(b * NT + ct) * KSEL + t] =
            (ssc[t * 4] + ssc[t * 4 + 1]) + (ssc[t * 4 + 2] + ssc[t * 4 + 3]);
}

// ---------------------------------------------------------------------------
// Kernel 4: softmax + Z = sum_k alpha_k * h_sel[k]
// ---------------------------------------------------------------------------
__global__ void finalize_kernel(const float* __restrict__ h, float* __restrict__ out) {
    const int b = blockIdx.x;
    const int t = threadIdx.x;

    __shared__ float scores[KSEL];
    __shared__ float alpha[KSEL];
    __shared__ int   ridx[KSEL];
    __shared__ float red[KSEL];

    if (t < KSEL) {
        float s = 0.f;
#pragma unroll
        for (int q = 0; q < NT; q++)
            s += g_partial[(b * NT + q) * KSEL + t];
        scores[t] = s;
        ridx[t] = b * NATOM + g_sel[b * KSEL + t];
        red[t] = s;
    }
    __syncthreads();
    for (int s = 64; s > 0; s >>= 1) {
        if (t < s) red[t] = fmaxf(red[t], red[t + s]);
        __syncthreads();
    }
    const float mx = red[0];
    __syncthreads();
    if (t < KSEL) {
        float e = expf(scores[t] - mx);
        alpha[t] = e;
        red[t] = e;
    }
    __syncthreads();
    for (int s = 64; s > 0; s >>= 1) {
        if (t < s) red[t] += red[t + s];
        __syncthreads();
    }
    const float inv = 1.0f / red[0];
    __syncthreads();
    if (t < KSEL) alpha[t] *= inv;
    __syncthreads();

    const int d0 = t * 4;
    float4 acc = make_float4(0.f, 0.f, 0.f, 0.f);
#pragma unroll 4
    for (int k = 0; k < KSEL; k++) {
        const float al = alpha[k];
        const float4 hv = *(const float4*)(h + (size_t)ridx[k] * DDIM + d0);
        acc.x = fmaf(al, hv.x, acc.x);
        acc.y = fmaf(al, hv.y, acc.y);
        acc.z = fmaf(al, hv.z, acc.z);
        acc.w = fmaf(al, hv.w, acc.w);
    }
    *(float4*)(out + (size_t)b * DDIM + d0) = acc;
}

// ---------------------------------------------------------------------------
// Entry point
// ---------------------------------------------------------------------------
extern "C" void kernel_launch(void* const* d_in, const int* in_sizes, int n_in,
                              void* d_out, int out_size) {
    const float* h      = (const float*)d_in[0];
    const float* coords = (const float*)d_in[1];
    const float* W      = (const float*)d_in[4];
    const float* bias   = (const float*)d_in[5];
    const float* v      = (const float*)d_in[6];
    float* out = (float*)d_out;

    cudaFuncSetAttribute(gemm_mma_kernel, cudaFuncAttributeMaxDynamicSharedMemorySize, SMEM_TOTAL);

    select_kernel<<<BGR, 512>>>(coords);
    prep_kernel<<<DDIM + BGR * KSEL, 256>>>(h, W);
    gemm_mma_kernel<<<dim3(NT, BGR), 256, SMEM_TOTAL>>>(bias, v);
    finalize_kernel<<<BGR, 256>>>(h, out);
}

// round 15
// speedup vs baseline: 1.2106x; 1.0046x over previous
#include <cuda_runtime.h>
#include <cuda_bf16.h>
#include <cstdint>
#include <cstddef>

// Problem constants (fixed by the reference setup)
#define BGR   256      // graphs
#define NATOM 512      // atoms per graph
#define NLIG  128      // ligand atoms per graph
#define NPROT 384      // protein atoms per graph
#define DDIM  1024     // feature dim
#define TOPK  64
#define KSEL  128      // 2*TOPK selected atoms per graph
#define NT    8        // n-tiles of 128 outputs
#define NTILE 128
#define NCHUNK 32      // K chunks of 32 bf16 cols

// ---------------------------------------------------------------------------
// Device scratch (no cudaMalloc allowed)
// ---------------------------------------------------------------------------
__device__ int   g_sel[BGR * KSEL];
__device__ float g_partial[BGR * NT * KSEL];
// hi/lo bf16 planes per row: [hi x1024 | lo x1024]
__device__ __nv_bfloat16 g_Ahl[(size_t)BGR * KSEL * 2 * DDIM];   // 128 MB
__device__ __nv_bfloat16 g_Whl[(size_t)DDIM * 2 * DDIM];         // 4 MB

// ---------------------------------------------------------------------------
// Helpers
// ---------------------------------------------------------------------------
__device__ __forceinline__ uint32_t smem_u32(const void* p) {
    uint32_t a;
    asm("{ .reg .u64 t; cvta.to.shared.u64 t, %1; cvt.u32.u64 %0, t; }" : "=r"(a) : "l"(p));
    return a;
}
__device__ __forceinline__ void cp_async16(uint32_t dst, const void* src) {
    asm volatile("cp.async.cg.shared.global [%0], [%1], 16;\n" :: "r"(dst), "l"(src) : "memory");
}
__device__ __forceinline__ void cp_commit() { asm volatile("cp.async.commit_group;\n" ::: "memory"); }
template <int N>
__device__ __forceinline__ void cp_wait() { asm volatile("cp.async.wait_group %0;\n" :: "n"(N) : "memory"); }

__device__ __forceinline__ void ldm4(uint32_t* r, uint32_t addr) {
    asm volatile("ldmatrix.sync.aligned.m8n8.x4.shared.b16 {%0,%1,%2,%3}, [%4];"
                 : "=r"(r[0]), "=r"(r[1]), "=r"(r[2]), "=r"(r[3]) : "r"(addr));
}
__device__ __forceinline__ void mma_bf16(float* d, const uint32_t* a, uint32_t b0, uint32_t b1) {
    asm volatile(
        "mma.sync.aligned.m16n8k16.row.col.f32.bf16.bf16.f32 "
        "{%0,%1,%2,%3}, {%4,%5,%6,%7}, {%8,%9}, {%0,%1,%2,%3};\n"
        : "+f"(d[0]), "+f"(d[1]), "+f"(d[2]), "+f"(d[3])
        : "r"(a[0]), "r"(a[1]), "r"(a[2]), "r"(a[3]), "r"(b0), "r"(b1));
}

// Accurate tanh that survives --use_fast_math.
__device__ __forceinline__ float tanh_acc(float x) {
    float e = exp2f(x * 2.8853900817779268f);
    return 1.0f - 2.0f / (e + 1.0f);
}

// hi/lo split store of 4 consecutive fp32 cols into [hi|lo] plane layout.
__device__ __forceinline__ void cvt_store4(__nv_bfloat16* dstrow, int t, float4 x) {
    const int col = t * 4;
    float xs[4] = {x.x, x.y, x.z, x.w};
    __nv_bfloat16 hi[4], lo[4];
#pragma unroll
    for (int j = 0; j < 4; j++) {
        hi[j] = __float2bfloat16(xs[j]);
        lo[j] = __float2bfloat16(xs[j] - __bfloat162float(hi[j]));
    }
    __nv_bfloat162 h01, h23, l01, l23;
    h01.x = hi[0]; h01.y = hi[1]; h23.x = hi[2]; h23.y = hi[3];
    l01.x = lo[0]; l01.y = lo[1]; l23.x = lo[2]; l23.y = lo[3];
    *(__nv_bfloat162*)(dstrow + col)            = h01;
    *(__nv_bfloat162*)(dstrow + col + 2)        = h23;
    *(__nv_bfloat162*)(dstrow + DDIM + col)     = l01;
    *(__nv_bfloat162*)(dstrow + DDIM + col + 2) = l23;
}

// ---------------------------------------------------------------------------
// Kernel 1: centroids + top-64 selection per graph. 512 threads/block:
// rank-count critical path is one key (384 compares) per thread.
// ---------------------------------------------------------------------------
__global__ void select_kernel(const float* __restrict__ coords) {
    const int b = blockIdx.x;
    const int t = threadIdx.x;

    __shared__ float cx[NATOM], cy[NATOM], cz[NATOM];
    __shared__ unsigned long long pkeys[NPROT];
    __shared__ unsigned long long lkeys[NLIG];
    __shared__ float r6[6][512];
    __shared__ float cent[6];

    const float* cg = coords + (size_t)b * NATOM * 3;
    for (int a = t; a < NATOM; a += 512) {
        cx[a] = cg[a * 3 + 0];
        cy[a] = cg[a * 3 + 1];
        cz[a] = cg[a * 3 + 2];
    }
    __syncthreads();

    float lsx = 0.f, lsy = 0.f, lsz = 0.f, psx = 0.f, psy = 0.f, psz = 0.f;
    for (int a = t; a < NATOM; a += 512) {
        if (a < NLIG) { lsx += cx[a]; lsy += cy[a]; lsz += cz[a]; }
        else          { psx += cx[a]; psy += cy[a]; psz += cz[a]; }
    }
    r6[0][t] = lsx; r6[1][t] = lsy; r6[2][t] = lsz;
    r6[3][t] = psx; r6[4][t] = psy; r6[5][t] = psz;
    __syncthreads();
    for (int s = 256; s > 0; s >>= 1) {
        if (t < s) {
#pragma unroll
            for (int c = 0; c < 6; c++) r6[c][t] += r6[c][t + s];
        }
        __syncthreads();
    }
    if (t == 0) {
        cent[0] = r6[0][0] / (float)NLIG;
        cent[1] = r6[1][0] / (float)NLIG;
        cent[2] = r6[2][0] / (float)NLIG;
        cent[3] = r6[3][0] / (float)NPROT;
        cent[4] = r6[4][0] / (float)NPROT;
        cent[5] = r6[5][0] / (float)NPROT;
    }
    __syncthreads();

    const float lcx = cent[0], lcy = cent[1], lcz = cent[2];
    const float pcx = cent[3], pcy = cent[4], pcz = cent[5];

    for (int i = t; i < NPROT; i += 512) {
        const int a = NLIG + i;
        float dx = cx[a] - lcx, dy = cy[a] - lcy, dz = cz[a] - lcz;
        float d2 = dx * dx + dy * dy + dz * dz;
        pkeys[i] = ((unsigned long long)__float_as_uint(d2) << 32) | (unsigned)a;
    }
    for (int i = t; i < NLIG; i += 512) {
        float dx = cx[i] - pcx, dy = cy[i] - pcy, dz = cz[i] - pcz;
        float d2 = dx * dx + dy * dy + dz * dz;
        lkeys[i] = ((unsigned long long)__float_as_uint(d2) << 32) | (unsigned)i;
    }
    __syncthreads();

    // rank-by-count; keys strictly distinct -> rank bijection, atomic-free
    if (t < NPROT) {
        const unsigned long long k = pkeys[t];
        int c = 0;
        for (int j = 0; j < NPROT; j++) c += (pkeys[j] < k);
        if (c < TOPK) g_sel[b * KSEL + c] = (int)(k & 0xffffffffull);
    }
    if (t < NLIG) {
        const unsigned long long k = lkeys[t];
        int c = 0;
        for (int j = 0; j < NLIG; j++) c += (lkeys[j] < k);
        if (c < TOPK) g_sel[b * KSEL + TOPK + c] = t;
    }
}

// ---------------------------------------------------------------------------
// Kernel 2: fused prep — W rows then gathered/selected h rows -> bf16 hi/lo.
// grid = DDIM + BGR*KSEL blocks, 256 threads.
// ---------------------------------------------------------------------------
__global__ void prep_kernel(const float* __restrict__ h, const float* __restrict__ W) {
    const int blk = blockIdx.x;
    const int t = threadIdx.x;
    if (blk < DDIM) {
        float4 x = *(const float4*)(W + (size_t)blk * DDIM + t * 4);
        cvt_store4(g_Whl + (size_t)blk * 2 * DDIM, t, x);
    } else {
        const int a = blk - DDIM;                 // 0..32767
        const int b = a >> 7, i = a & 127;
        const int src = b * NATOM + g_sel[b * KSEL + i];
        float4 x = *(const float4*)(h + (size_t)src * DDIM + t * 4);
        cvt_store4(g_Ahl + (size_t)a * 2 * DDIM, t, x);
    }
}

// ---------------------------------------------------------------------------
// Kernel 3: mma.sync bf16 hi/lo-split GEMM + fused bias/tanh/v-dot.
// Grid (8 n-tiles, 256 graphs), 256 threads (8 warps, 2m x 4n of 64x32).
// CTA tile: M=128 x N=128 x K=1024 (x3 split products). 2 CTAs/SM.
// SMEM: 3-stage pipelined K-chunks; XOR-swizzled 16B segments, no padding.
// One __syncthreads per chunk; warp-staggered k16 order; cp.async for c+2
// issued between the two k16 computes; precomputed ldmatrix addresses.
// ---------------------------------------------------------------------------
#define PLANE_B  (128 * 64)             // 8192 bytes per plane (128 rows x 64B)
#define ABYTES   (2 * PLANE_B)          // 16384 (A hi + A lo)
#define BUFB     (4 * PLANE_B)          // 32768 (A hi/lo + B hi/lo)
#define NSTAGE   3
#define SM_BIAS  (NSTAGE * BUFB)        // 98304 : float[128]
#define SM_V     (SM_BIAS + 512)
#define SM_SC    (SM_V + 512)           // float[128*4]
#define SMEM_TOTAL (SM_SC + 2048)       // 101376  (x2 CTAs = 202752 <= 228K)

// swizzled in-plane byte offset for (row, seg16)
#define SWZ_OFF(row, seg) ((row) * 64 + ((((seg) ^ (((row) >> 1) & 3))) << 4))

__global__ void __launch_bounds__(256, 2)
gemm_mma_kernel(const float* __restrict__ bias, const float* __restrict__ v) {
    extern __shared__ char smem[];
    const int ct = blockIdx.x;       // n-tile 0..7
    const int b  = blockIdx.y;       // graph
    const int t  = threadIdx.x;
    const int lane = t & 31, wid = t >> 5;
    const int wm = wid >> 2, wn = wid & 3;   // warp 64x32 tile coords
    const uint32_t sbase = smem_u32(smem);

    float* sbias = (float*)(smem + SM_BIAS);
    float* sv    = (float*)(smem + SM_V);
    float* ssc   = (float*)(smem + SM_SC);
    if (t < NTILE) {
        sbias[t] = bias[ct * NTILE + t];
        sv[t]    = v[ct * NTILE + t];
    }

    const char* asrc = (const char*)(g_Ahl) + (size_t)b * KSEL * 4096;    // 2048 bf16/row
    const char* bsrc = (const char*)(g_Whl) + (size_t)ct * NTILE * 4096;

    // chunk loader: 2048 x 16B segments (A: 1024, B: 1024), 8 per thread
    auto load_chunk = [&](int c, int buf) {
        const uint32_t dstbase = sbase + buf * BUFB;
        const int coff = c * 64;   // 32 bf16 = 64 B within a plane
#pragma unroll
        for (int it = 0; it < 8; it++) {
            const int s = t + it * 256;
            const bool isA = s < 1024;
            const int s2 = isA ? s : s - 1024;
            const int plane = s2 >> 9, row = (s2 >> 2) & 127, seg = s2 & 3;
            const char* src = (isA ? asrc : bsrc) + (size_t)row * 4096 + plane * 2048 + coff + seg * 16;
            const uint32_t dst = dstbase + (isA ? 0 : ABYTES) + plane * PLANE_B + SWZ_OFF(row, seg);
            cp_async16(dst, src);
        }
        cp_commit();
    };

    // per-thread ldmatrix swizzled byte offsets, precomputed for both k16 halves
    uint32_t a_off[4][2], b_off[2][2];
#pragma unroll
    for (int mt = 0; mt < 4; mt++) {
        const int row = wm * 64 + mt * 16 + (lane & 15);
        const int s0 = lane >> 4;
#pragma unroll
        for (int k16 = 0; k16 < 2; k16++)
            a_off[mt][k16] = (uint32_t)SWZ_OFF(row, s0 + 2 * k16);
    }
#pragma unroll
    for (int np = 0; np < 2; np++) {
        const int row = wn * 32 + np * 16 + (lane & 7) + ((lane >> 4) << 3);
        const int s0 = (lane >> 3) & 1;
#pragma unroll
        for (int k16 = 0; k16 < 2; k16++)
            b_off[np][k16] = (uint32_t)SWZ_OFF(row, s0 + 2 * k16);
    }

    float acc[4][4][4];
#pragma unroll
    for (int mt = 0; mt < 4; mt++)
#pragma unroll
        for (int nt = 0; nt < 4; nt++)
#pragma unroll
            for (int q = 0; q < 4; q++) acc[mt][nt][q] = 0.f;

    // compute one k16 half of the current chunk
    auto compute_k16 = [&](uint32_t abase, uint32_t bbase, int k16) {
        uint32_t Af[4][4], Bh[2][4], Bl[2][4];
#pragma unroll
        for (int mt = 0; mt < 4; mt++) ldm4(Af[mt], abase + a_off[mt][k16]);
#pragma unroll
        for (int np = 0; np < 2; np++) ldm4(Bh[np], bbase + b_off[np][k16]);
#pragma unroll
        for (int np = 0; np < 2; np++) ldm4(Bl[np], bbase + PLANE_B + b_off[np][k16]);
        // Ahi * Bhi
#pragma unroll
        for (int mt = 0; mt < 4; mt++)
#pragma unroll
            for (int np = 0; np < 2; np++) {
                mma_bf16(acc[mt][2 * np],     Af[mt], Bh[np][0], Bh[np][1]);
                mma_bf16(acc[mt][2 * np + 1], Af[mt], Bh[np][2], Bh[np][3]);
            }
        // Ahi * Blo
#pragma unroll
        for (int mt = 0; mt < 4; mt++)
#pragma unroll
            for (int np = 0; np < 2; np++) {
                mma_bf16(acc[mt][2 * np],     Af[mt], Bl[np][0], Bl[np][1]);
                mma_bf16(acc[mt][2 * np + 1], Af[mt], Bl[np][2], Bl[np][3]);
            }
        // Alo * Bhi (Af reused destructively: peak frag regs stay at 32)
#pragma unroll
        for (int mt = 0; mt < 4; mt++) ldm4(Af[mt], abase + PLANE_B + a_off[mt][k16]);
#pragma unroll
        for (int mt = 0; mt < 4; mt++)
#pragma unroll
            for (int np = 0; np < 2; np++) {
                mma_bf16(acc[mt][2 * np],     Af[mt], Bh[np][0], Bh[np][1]);
                mma_bf16(acc[mt][2 * np + 1], Af[mt], Bh[np][2], Bh[np][3]);
            }
    };

    load_chunk(0, 0);
    load_chunk(1, 1);

    const int kfirst = (wid >> 2) & 1;   // SMSP siblings (wid, wid+4) opposite
    int buf_c = 0, buf_n2 = 2;           // buffer of chunk c, buffer for chunk c+2
    for (int c = 0; c < NCHUNK; c++) {
        if (c + 1 < NCHUNK) cp_wait<1>(); else cp_wait<0>();
        __syncthreads();

        const uint32_t abase = sbase + buf_c * BUFB;
        const uint32_t bbase = abase + ABYTES;

        compute_k16(abase, bbase, kfirst);
        if (c + 2 < NCHUNK) load_chunk(c + 2, buf_n2);
        compute_k16(abase, bbase, kfirst ^ 1);

        const int nb = buf_c + 1;
        buf_c  = (nb == NSTAGE) ? 0 : nb;
        const int nn = buf_n2 + 1;
        buf_n2 = (nn == NSTAGE) ? 0 : nn;
    }

    // Epilogue: bias + tanh + v-dot, reduce over this CTA's 128 cols
#pragma unroll
    for (int mt = 0; mt < 4; mt++) {
#pragma unroll
        for (int half = 0; half < 2; half++) {
            float s = 0.f;
#pragma unroll
            for (int nt = 0; nt < 4; nt++) {
                const int n = wn * 32 + nt * 8 + 2 * (lane & 3);
                const float* a2 = &acc[mt][nt][half * 2];
                s = fmaf(sv[n],     tanh_acc(a2[0] + sbias[n]),     s);
                s = fmaf(sv[n + 1], tanh_acc(a2[1] + sbias[n + 1]), s);
            }
            s += __shfl_xor_sync(0xffffffffu, s, 1);
            s += __shfl_xor_sync(0xffffffffu, s, 2);
            if ((lane & 3) == 0) {
                const int row = wm * 64 + mt * 16 + (lane >> 2) + half * 8;
                ssc[row * 4 + wn] = s;
            }
        }
    }
    __syncthreads();
    if (t < KSEL)
        g_partial[(b * NT + ct) * KSEL + t] =
            (ssc[t * 4] + ssc[t * 4 + 1]) + (ssc[t * 4 + 2] + ssc[t * 4 + 3]);
}

// ---------------------------------------------------------------------------
// Kernel 4: softmax + Z = sum_k alpha_k * h_sel[k].
// 4 blocks per graph; each block covers 64 float4 columns with a 4-way
// k-split (thread = kslice*64 + col), then float4 smem tree-reduce.
// Softmax recomputed redundantly per block (4 KB of g_partial, negligible).
// ---------------------------------------------------------------------------
__global__ void finalize_kernel(const float* __restrict__ h, float* __restrict__ out) {
    const int blk = blockIdx.x;
    const int b = blk >> 2;          // graph
    const int q = blk & 3;           // feature quarter
    const int t = threadIdx.x;
    const int col = t & 63;          // float4 column within quarter
    const int ks  = t >> 6;          // k-slice 0..3

    __shared__ float scores[KSEL];
    __shared__ float alpha[KSEL];
    __shared__ int   ridx[KSEL];
    __shared__ float red[KSEL];
    __shared__ float4 sred[256];

    if (t < KSEL) {
        float s = 0.f;
#pragma unroll
        for (int p = 0; p < NT; p++)
            s += g_partial[(b * NT + p) * KSEL + t];
        scores[t] = s;
        ridx[t] = b * NATOM + g_sel[b * KSEL + t];
        red[t] = s;
    }
    __syncthreads();
    for (int s = 64; s > 0; s >>= 1) {
        if (t < s) red[t] = fmaxf(red[t], red[t + s]);
        __syncthreads();
    }
    const float mx = red[0];
    __syncthreads();
    if (t < KSEL) {
        float e = expf(scores[t] - mx);
        alpha[t] = e;
        red[t] = e;
    }
    __syncthreads();
    for (int s = 64; s > 0; s >>= 1) {
        if (t < s) red[t] += red[t + s];
        __syncthreads();
    }
    const float inv = 1.0f / red[0];
    __syncthreads();
    if (t < KSEL) alpha[t] *= inv;
    __syncthreads();

    // partial Z over this thread's 32 k values
    const int d0 = q * 256 + col * 4;
    float4 acc = make_float4(0.f, 0.f, 0.f, 0.f);
#pragma unroll 4
    for (int k = ks * 32; k < ks * 32 + 32; k++) {
        const float al = alpha[k];
        const float4 hv = *(const float4*)(h + (size_t)ridx[k] * DDIM + d0);
        acc.x = fmaf(al, hv.x, acc.x);
        acc.y = fmaf(al, hv.y, acc.y);
        acc.z = fmaf(al, hv.z, acc.z);
        acc.w = fmaf(al, hv.w, acc.w);
    }
    sred[t] = acc;
    __syncthreads();
    if (t < 128) {
        float4 a0 = sred[t], a1 = sred[t + 128];
        a0.x += a1.x; a0.y += a1.y; a0.z += a1.z; a0.w += a1.w;
        sred[t] = a0;
    }
    __syncthreads();
    if (t < 64) {
        float4 a0 = sred[t], a1 = sred[t + 64];
        a0.x += a1.x; a0.y += a1.y; a0.z += a1.z; a0.w += a1.w;
        *(float4*)(out + (size_t)b * DDIM + d0) = a0;
    }
}

// ---------------------------------------------------------------------------
// Entry point
// ---------------------------------------------------------------------------
extern "C" void kernel_launch(void* const* d_in, const int* in_sizes, int n_in,
                              void* d_out, int out_size) {
    const float* h      = (const float*)d_in[0];
    const float* coords = (const float*)d_in[1];
    const float* W      = (const float*)d_in[4];
    const float* bias   = (const float*)d_in[5];
    const float* v      = (const float*)d_in[6];
    float* out = (float*)d_out;

    cudaFuncSetAttribute(gemm_mma_kernel, cudaFuncAttributeMaxDynamicSharedMemorySize, SMEM_TOTAL);

    select_kernel<<<BGR, 512>>>(coords);
    prep_kernel<<<DDIM + BGR * KSEL, 256>>>(h, W);
    gemm_mma_kernel<<<dim3(NT, BGR), 256, SMEM_TOTAL>>>(bias, v);
    finalize_kernel<<<BGR * 4, 256>>>(h, out);
}